// round 5
// baseline (speedup 1.0000x reference)
#include <cuda_runtime.h>
#include <cuda_bf16.h>

#define MAXN 50000
#define MAXE 800000
#define F 128

// Scratch (static device globals -- no allocation)
__device__ int   g_deg[MAXN];
__device__ int   g_off[MAXN + 1];
__device__ int   g_cur[MAXN];
__device__ int   g_adj[MAXE];
__device__ float g_hn[(size_t)MAXN * F];   // mean-aggregated neighbor features
__device__ float g_h1[(size_t)MAXN * F];   // layer-1 output
__device__ float g_h2[(size_t)MAXN * F];   // layer-2 output

// ---------------------------------------------------------------------------
// CSR build
// ---------------------------------------------------------------------------
__global__ void k_zero_deg(int n) {
    int i = blockIdx.x * blockDim.x + threadIdx.x;
    if (i < n) g_deg[i] = 0;
}

__global__ void k_count_deg(const int* __restrict__ dst, int E) {
    int i = blockIdx.x * blockDim.x + threadIdx.x;
    if (i < E) atomicAdd(&g_deg[dst[i]], 1);
}

// Single-block exclusive scan over g_deg -> g_off / g_cur. n <= 50176.
__global__ void k_scan(int n, int E) {
    __shared__ int sums[1024];
    int tid = threadIdx.x;
    int chunk = (n + 1023) >> 10;
    int b = tid * chunk;
    int e = min(b + chunk, n);
    int s = 0;
    for (int i = b; i < e; ++i) s += g_deg[i];
    sums[tid] = s;
    __syncthreads();
    for (int o = 1; o < 1024; o <<= 1) {
        int v = (tid >= o) ? sums[tid - o] : 0;
        __syncthreads();
        sums[tid] += v;
        __syncthreads();
    }
    int run = sums[tid] - s;   // exclusive prefix
    for (int i = b; i < e; ++i) {
        g_off[i] = run;
        g_cur[i] = run;
        run += g_deg[i];
    }
    if (tid == 1023) g_off[n] = E;
}

__global__ void k_fill_adj(const int* __restrict__ src, const int* __restrict__ dst, int E) {
    int i = blockIdx.x * blockDim.x + threadIdx.x;
    if (i < E) {
        int p = atomicAdd(&g_cur[dst[i]], 1);
        g_adj[p] = src[i];
    }
}

// ---------------------------------------------------------------------------
// Mean aggregation (pull via CSR): one block per node, thread = feature col.
// layer==0: feat = x (external).  layer==1: feat = g_h1.
// ---------------------------------------------------------------------------
__global__ void k_agg_mean(const float* __restrict__ xext, int layer) {
    const float* __restrict__ feat = layer ? g_h1 : xext;
    int node = blockIdx.x;
    int c = threadIdx.x;
    int s = g_off[node];
    int e = g_off[node + 1];
    float acc = 0.f;
    int j = s;
    for (; j + 4 <= e; j += 4) {
        int s0 = g_adj[j], s1 = g_adj[j + 1], s2 = g_adj[j + 2], s3 = g_adj[j + 3];
        float v0 = feat[(size_t)s0 * F + c];
        float v1 = feat[(size_t)s1 * F + c];
        float v2 = feat[(size_t)s2 * F + c];
        float v3 = feat[(size_t)s3 * F + c];
        acc += (v0 + v1) + (v2 + v3);
    }
    for (; j < e; ++j) acc += feat[(size_t)g_adj[j] * F + c];
    int d = e - s;
    g_hn[(size_t)node * F + c] = d ? acc * (1.f / (float)d) : 0.f;
}

// ---------------------------------------------------------------------------
// Fused dual-GEMM + bias + ReLU:
//   C[m][n] = relu( sum_k A1[m][k]*W1[n][k] + sum_k A2[m][k]*W2[n][k] + bias[n] )
// A1 = (layer ? g_h1 : x), A2 = g_hn, C = (layer ? g_h2 : g_h1).
// Tile: 128(M) x 128(N) x 32(K), 256 threads, 8x8 register tile/thread.
// ---------------------------------------------------------------------------
#define KB 32
#define PAD 132   // 128 + 4 pad, keeps 16B alignment, breaks bank conflicts

__global__ __launch_bounds__(256) void k_gemm2(
    const float* __restrict__ xext,
    const float* __restrict__ W1, const float* __restrict__ W2,
    const float* __restrict__ bias, int M, int layer)
{
    __shared__ float At[KB][PAD];
    __shared__ float Wt[KB][PAD];

    const float* __restrict__ A1 = layer ? g_h1 : xext;
    const float* __restrict__ A2 = g_hn;
    float* __restrict__ C = layer ? g_h2 : g_h1;

    int m0 = blockIdx.x * 128;
    int tid = threadIdx.x;
    int tn = tid & 15;        // 0..15  (column group, fast-varying for coalesced C stores)
    int tm = tid >> 4;        // 0..15  (row group)

    int lr = tid >> 3;        // 0..31 : row within 32-row load slab
    int lk = (tid & 7) * 4;   // 0,4,...,28 : k offset (float4)

    float acc[8][8];
#pragma unroll
    for (int i = 0; i < 8; ++i)
#pragma unroll
        for (int j = 0; j < 8; ++j) acc[i][j] = 0.f;

#pragma unroll 1
    for (int srcI = 0; srcI < 2; ++srcI) {
        const float* __restrict__ A = srcI ? A2 : A1;
        const float* __restrict__ W = srcI ? W2 : W1;
#pragma unroll 1
        for (int kb = 0; kb < F; kb += KB) {
            __syncthreads();
            // A tile: rows m0+lr+p*32, cols kb+lk..+3, stored transposed At[k][m]
#pragma unroll
            for (int p = 0; p < 4; ++p) {
                int m = m0 + lr + p * 32;
                float4 v = make_float4(0.f, 0.f, 0.f, 0.f);
                if (m < M) v = *(const float4*)&A[(size_t)m * F + kb + lk];
                int mm = lr + p * 32;
                At[lk + 0][mm] = v.x;
                At[lk + 1][mm] = v.y;
                At[lk + 2][mm] = v.z;
                At[lk + 3][mm] = v.w;
            }
            // W tile: W is [128][128] row-major [n][k]; store transposed Wt[k][n]
#pragma unroll
            for (int p = 0; p < 4; ++p) {
                int n = lr + p * 32;
                float4 v = *(const float4*)&W[n * F + kb + lk];
                Wt[lk + 0][n] = v.x;
                Wt[lk + 1][n] = v.y;
                Wt[lk + 2][n] = v.z;
                Wt[lk + 3][n] = v.w;
            }
            __syncthreads();

#pragma unroll
            for (int kk = 0; kk < KB; ++kk) {
                float4 a0 = *(const float4*)&At[kk][tm * 8];
                float4 a1 = *(const float4*)&At[kk][tm * 8 + 4];
                float4 w0 = *(const float4*)&Wt[kk][tn * 8];
                float4 w1 = *(const float4*)&Wt[kk][tn * 8 + 4];
                float a[8] = {a0.x, a0.y, a0.z, a0.w, a1.x, a1.y, a1.z, a1.w};
                float w[8] = {w0.x, w0.y, w0.z, w0.w, w1.x, w1.y, w1.z, w1.w};
#pragma unroll
                for (int i = 0; i < 8; ++i)
#pragma unroll
                    for (int j = 0; j < 8; ++j)
                        acc[i][j] = fmaf(a[i], w[j], acc[i][j]);
            }
        }
    }

    // Epilogue: bias + relu, float4 stores
    float bv[8];
#pragma unroll
    for (int j = 0; j < 8; ++j) bv[j] = bias[tn * 8 + j];

#pragma unroll
    for (int i = 0; i < 8; ++i) {
        int m = m0 + tm * 8 + i;
        if (m < M) {
            float4 o0, o1;
            o0.x = fmaxf(acc[i][0] + bv[0], 0.f);
            o0.y = fmaxf(acc[i][1] + bv[1], 0.f);
            o0.z = fmaxf(acc[i][2] + bv[2], 0.f);
            o0.w = fmaxf(acc[i][3] + bv[3], 0.f);
            o1.x = fmaxf(acc[i][4] + bv[4], 0.f);
            o1.y = fmaxf(acc[i][5] + bv[5], 0.f);
            o1.z = fmaxf(acc[i][6] + bv[6], 0.f);
            o1.w = fmaxf(acc[i][7] + bv[7], 0.f);
            *(float4*)&C[(size_t)m * F + tn * 8] = o0;
            *(float4*)&C[(size_t)m * F + tn * 8 + 4] = o1;
        }
    }
}

// ---------------------------------------------------------------------------
// Readout: states max-pool + action row, dot with Wfc, +bfc -> scalar
// ---------------------------------------------------------------------------
__global__ void k_readout(const int* __restrict__ states, int S,
                          const int* __restrict__ actions,
                          const float* __restrict__ Wfc,
                          const float* __restrict__ bfc,
                          float* __restrict__ out)
{
    __shared__ int   snode[512];
    __shared__ float red[128];
    int c = threadIdx.x;   // 128 threads
    for (int i = c; i < S; i += 128) snode[i] = states[i];
    __syncthreads();

    float m = -3.4e38f;
    int s2 = 0;
    for (; s2 + 4 <= S; s2 += 4) {
        float v0 = g_h2[(size_t)snode[s2 + 0] * F + c];
        float v1 = g_h2[(size_t)snode[s2 + 1] * F + c];
        float v2 = g_h2[(size_t)snode[s2 + 2] * F + c];
        float v3 = g_h2[(size_t)snode[s2 + 3] * F + c];
        m = fmaxf(m, fmaxf(fmaxf(v0, v1), fmaxf(v2, v3)));
    }
    for (; s2 < S; ++s2) m = fmaxf(m, g_h2[(size_t)snode[s2] * F + c]);

    float a = g_h2[(size_t)actions[0] * F + c];
    float p = m * Wfc[c] + a * Wfc[F + c];
    red[c] = p;
    __syncthreads();
    for (int o = 64; o > 0; o >>= 1) {
        if (c < o) red[c] += red[c + o];
        __syncthreads();
    }
    if (c == 0) out[0] = red[0] + bfc[0];
}

// ---------------------------------------------------------------------------
extern "C" void kernel_launch(void* const* d_in, const int* in_sizes, int n_in,
                              void* d_out, int out_size)
{
    const float* x       = (const float*)d_in[0];
    const int*   esrc    = (const int*)d_in[1];
    const int*   edst    = (const int*)d_in[2];
    const int*   states  = (const int*)d_in[3];
    const int*   actions = (const int*)d_in[4];
    const float* W1s     = (const float*)d_in[5];
    const float* W1n     = (const float*)d_in[6];
    const float* b1      = (const float*)d_in[7];
    const float* W2s     = (const float*)d_in[8];
    const float* W2n     = (const float*)d_in[9];
    const float* b2      = (const float*)d_in[10];
    const float* Wfc     = (const float*)d_in[11];
    const float* bfc     = (const float*)d_in[12];
    float* out = (float*)d_out;

    int N = in_sizes[0] / F;
    int E = in_sizes[1];
    int S = in_sizes[3];

    // CSR build (per launch; identical work every call)
    k_zero_deg<<<(N + 255) / 256, 256>>>(N);
    k_count_deg<<<(E + 255) / 256, 256>>>(edst, E);
    k_scan<<<1, 1024>>>(N, E);
    k_fill_adj<<<(E + 255) / 256, 256>>>(esrc, edst, E);

    int gemm_blocks = (N + 127) / 128;

    // Layer 1
    k_agg_mean<<<N, 128>>>(x, 0);
    k_gemm2<<<gemm_blocks, 256>>>(x, W1s, W1n, b1, N, 0);

    // Layer 2
    k_agg_mean<<<N, 128>>>(x, 1);
    k_gemm2<<<gemm_blocks, 256>>>(x, W2s, W2n, b2, N, 1);

    // Readout
    k_readout<<<1, 128>>>(states, S, actions, Wfc, bfc, out);
}

// round 6
// speedup vs baseline: 1.3000x; 1.3000x over previous
#include <cuda_runtime.h>
#include <cuda_bf16.h>

typedef unsigned long long u64;

#define MAXN 50000
#define MAXE 800000
#define F 128

// Scratch (static device globals -- no allocation)
__device__ int   g_deg[MAXN];
__device__ int   g_off[MAXN + 1];
__device__ int   g_cur[MAXN];
__device__ int   g_adj[MAXE];
__device__ float g_hn[(size_t)MAXN * F];   // mean-aggregated neighbor features
__device__ float g_h1[(size_t)MAXN * F];   // layer-1 output
__device__ float g_h2[(size_t)MAXN * F];   // layer-2 output

// ---------------------------------------------------------------------------
// CSR build
// ---------------------------------------------------------------------------
__global__ void k_zero_deg(int n) {
    int i = blockIdx.x * blockDim.x + threadIdx.x;
    if (i < n) g_deg[i] = 0;
}

__global__ void k_count_deg(const int* __restrict__ dst, int E) {
    int i = blockIdx.x * blockDim.x + threadIdx.x;
    if (i < E) atomicAdd(&g_deg[dst[i]], 1);
}

// Single-block exclusive scan over g_deg -> g_off / g_cur. n <= 50176.
__global__ void k_scan(int n, int E) {
    __shared__ int sums[1024];
    int tid = threadIdx.x;
    int chunk = (n + 1023) >> 10;
    int b = tid * chunk;
    int e = min(b + chunk, n);
    int s = 0;
    for (int i = b; i < e; ++i) s += g_deg[i];
    sums[tid] = s;
    __syncthreads();
    for (int o = 1; o < 1024; o <<= 1) {
        int v = (tid >= o) ? sums[tid - o] : 0;
        __syncthreads();
        sums[tid] += v;
        __syncthreads();
    }
    int run = sums[tid] - s;   // exclusive prefix
    for (int i = b; i < e; ++i) {
        g_off[i] = run;
        g_cur[i] = run;
        run += g_deg[i];
    }
    if (tid == 1023) g_off[n] = E;
}

__global__ void k_fill_adj(const int* __restrict__ src, const int* __restrict__ dst, int E) {
    int i = blockIdx.x * blockDim.x + threadIdx.x;
    if (i < E) {
        int p = atomicAdd(&g_cur[dst[i]], 1);
        g_adj[p] = src[i];
    }
}

// ---------------------------------------------------------------------------
// Mean aggregation (pull via CSR): one WARP per node, lane = 4-col float4 slice.
// layer==0: feat = x (external).  layer==1: feat = g_h1.
// ---------------------------------------------------------------------------
__global__ __launch_bounds__(128) void k_agg_mean(const float* __restrict__ xext,
                                                  int layer, int N) {
    const float* __restrict__ feat = layer ? g_h1 : xext;
    int node = blockIdx.x * 4 + (threadIdx.x >> 5);
    if (node >= N) return;
    int c = (threadIdx.x & 31) * 4;

    int s = g_off[node];
    int e = g_off[node + 1];
    float4 acc = make_float4(0.f, 0.f, 0.f, 0.f);

    int j = s;
    for (; j + 2 <= e; j += 2) {
        int s0 = g_adj[j], s1 = g_adj[j + 1];
        float4 v0 = *(const float4*)&feat[(size_t)s0 * F + c];
        float4 v1 = *(const float4*)&feat[(size_t)s1 * F + c];
        acc.x += v0.x + v1.x;
        acc.y += v0.y + v1.y;
        acc.z += v0.z + v1.z;
        acc.w += v0.w + v1.w;
    }
    if (j < e) {
        float4 v = *(const float4*)&feat[(size_t)g_adj[j] * F + c];
        acc.x += v.x; acc.y += v.y; acc.z += v.z; acc.w += v.w;
    }

    int d = e - s;
    float inv = d ? 1.f / (float)d : 0.f;
    acc.x *= inv; acc.y *= inv; acc.z *= inv; acc.w *= inv;
    *(float4*)&g_hn[(size_t)node * F + c] = acc;
}

// ---------------------------------------------------------------------------
// Fused dual-GEMM + bias + ReLU, inner loop in packed fma.rn.f32x2:
//   C[m][n] = relu( sum_k A1[m][k]*W1[n][k] + sum_k A2[m][k]*W2[n][k] + bias[n] )
// Tile: 128(M) x 128(N) x 32(K), 256 threads, 8(M)x8(N) register tile/thread,
// N-dim packed in pairs (8x4 u64 accumulators).
// ---------------------------------------------------------------------------
#define KB 32
#define PAD 132   // 128 + 4 pad, keeps 16B alignment, breaks bank conflicts

__device__ __forceinline__ void ffma2(u64& d, u64 a, u64 b) {
    asm("fma.rn.f32x2 %0, %1, %2, %0;" : "+l"(d) : "l"(a), "l"(b));
}
__device__ __forceinline__ u64 bcast2(float a) {
    u64 d;
    unsigned r = __float_as_uint(a);
    asm("mov.b64 %0, {%1, %1};" : "=l"(d) : "r"(r));
    return d;
}

__global__ __launch_bounds__(256) void k_gemm2(
    const float* __restrict__ xext,
    const float* __restrict__ W1, const float* __restrict__ W2,
    const float* __restrict__ bias, int M, int layer)
{
    __shared__ float At[KB][PAD];
    __shared__ float Wt[KB][PAD];

    const float* __restrict__ A1 = layer ? g_h1 : xext;
    const float* __restrict__ A2 = g_hn;
    float* __restrict__ C = layer ? g_h2 : g_h1;

    int m0 = blockIdx.x * 128;
    int tid = threadIdx.x;
    int tn = tid & 15;        // 0..15  column group (fast-varying -> coalesced C)
    int tm = tid >> 4;        // 0..15  row group

    int lr = tid >> 3;        // 0..31 : row within 32-row load slab
    int lk = (tid & 7) * 4;   // 0,4,...,28 : k offset (float4)

    u64 acc2[8][4];           // [m-row][n-pair], low lane = even col
#pragma unroll
    for (int i = 0; i < 8; ++i)
#pragma unroll
        for (int j = 0; j < 4; ++j) acc2[i][j] = 0ull;

#pragma unroll 1
    for (int srcI = 0; srcI < 2; ++srcI) {
        const float* __restrict__ A = srcI ? A2 : A1;
        const float* __restrict__ W = srcI ? W2 : W1;
#pragma unroll 1
        for (int kb = 0; kb < F; kb += KB) {
            __syncthreads();
            // A tile: rows m0+lr+p*32, cols kb+lk..+3, stored transposed At[k][m]
#pragma unroll
            for (int p = 0; p < 4; ++p) {
                int m = m0 + lr + p * 32;
                float4 v = make_float4(0.f, 0.f, 0.f, 0.f);
                if (m < M) v = *(const float4*)&A[(size_t)m * F + kb + lk];
                int mm = lr + p * 32;
                At[lk + 0][mm] = v.x;
                At[lk + 1][mm] = v.y;
                At[lk + 2][mm] = v.z;
                At[lk + 3][mm] = v.w;
            }
            // W tile: W is [128][128] row-major [n][k]; store transposed Wt[k][n]
#pragma unroll
            for (int p = 0; p < 4; ++p) {
                int n = lr + p * 32;
                float4 v = *(const float4*)&W[n * F + kb + lk];
                Wt[lk + 0][n] = v.x;
                Wt[lk + 1][n] = v.y;
                Wt[lk + 2][n] = v.z;
                Wt[lk + 3][n] = v.w;
            }
            __syncthreads();

#pragma unroll
            for (int kk = 0; kk < KB; ++kk) {
                float4 a0 = *(const float4*)&At[kk][tm * 8];
                float4 a1 = *(const float4*)&At[kk][tm * 8 + 4];
                // w pairs come packed straight out of shared memory
                const u64* wp = (const u64*)&Wt[kk][tn * 8];
                u64 w2[4];
#pragma unroll
                for (int j = 0; j < 4; ++j) w2[j] = wp[j];

                u64 ap[8];
                ap[0] = bcast2(a0.x); ap[1] = bcast2(a0.y);
                ap[2] = bcast2(a0.z); ap[3] = bcast2(a0.w);
                ap[4] = bcast2(a1.x); ap[5] = bcast2(a1.y);
                ap[6] = bcast2(a1.z); ap[7] = bcast2(a1.w);
#pragma unroll
                for (int i = 0; i < 8; ++i)
#pragma unroll
                    for (int j = 0; j < 4; ++j)
                        ffma2(acc2[i][j], ap[i], w2[j]);
            }
        }
    }

    // Epilogue: unpack, bias + relu, float4 stores
    float bv[8];
#pragma unroll
    for (int j = 0; j < 8; ++j) bv[j] = bias[tn * 8 + j];

#pragma unroll
    for (int i = 0; i < 8; ++i) {
        int m = m0 + tm * 8 + i;
        if (m < M) {
            float c8[8];
#pragma unroll
            for (int j = 0; j < 4; ++j) {
                u64 v = acc2[i][j];
                c8[2 * j + 0] = __uint_as_float((unsigned)v);
                c8[2 * j + 1] = __uint_as_float((unsigned)(v >> 32));
            }
            float4 o0, o1;
            o0.x = fmaxf(c8[0] + bv[0], 0.f);
            o0.y = fmaxf(c8[1] + bv[1], 0.f);
            o0.z = fmaxf(c8[2] + bv[2], 0.f);
            o0.w = fmaxf(c8[3] + bv[3], 0.f);
            o1.x = fmaxf(c8[4] + bv[4], 0.f);
            o1.y = fmaxf(c8[5] + bv[5], 0.f);
            o1.z = fmaxf(c8[6] + bv[6], 0.f);
            o1.w = fmaxf(c8[7] + bv[7], 0.f);
            *(float4*)&C[(size_t)m * F + tn * 8] = o0;
            *(float4*)&C[(size_t)m * F + tn * 8 + 4] = o1;
        }
    }
}

// ---------------------------------------------------------------------------
// Readout: states max-pool + action row, dot with Wfc, +bfc -> scalar
// ---------------------------------------------------------------------------
__global__ void k_readout(const int* __restrict__ states, int S,
                          const int* __restrict__ actions,
                          const float* __restrict__ Wfc,
                          const float* __restrict__ bfc,
                          float* __restrict__ out)
{
    __shared__ int   snode[512];
    __shared__ float red[128];
    int c = threadIdx.x;   // 128 threads
    for (int i = c; i < S; i += 128) snode[i] = states[i];
    __syncthreads();

    float m = -3.4e38f;
    int s2 = 0;
    for (; s2 + 4 <= S; s2 += 4) {
        float v0 = g_h2[(size_t)snode[s2 + 0] * F + c];
        float v1 = g_h2[(size_t)snode[s2 + 1] * F + c];
        float v2 = g_h2[(size_t)snode[s2 + 2] * F + c];
        float v3 = g_h2[(size_t)snode[s2 + 3] * F + c];
        m = fmaxf(m, fmaxf(fmaxf(v0, v1), fmaxf(v2, v3)));
    }
    for (; s2 < S; ++s2) m = fmaxf(m, g_h2[(size_t)snode[s2] * F + c]);

    float a = g_h2[(size_t)actions[0] * F + c];
    float p = m * Wfc[c] + a * Wfc[F + c];
    red[c] = p;
    __syncthreads();
    for (int o = 64; o > 0; o >>= 1) {
        if (c < o) red[c] += red[c + o];
        __syncthreads();
    }
    if (c == 0) out[0] = red[0] + bfc[0];
}

// ---------------------------------------------------------------------------
extern "C" void kernel_launch(void* const* d_in, const int* in_sizes, int n_in,
                              void* d_out, int out_size)
{
    const float* x       = (const float*)d_in[0];
    const int*   esrc    = (const int*)d_in[1];
    const int*   edst    = (const int*)d_in[2];
    const int*   states  = (const int*)d_in[3];
    const int*   actions = (const int*)d_in[4];
    const float* W1s     = (const float*)d_in[5];
    const float* W1n     = (const float*)d_in[6];
    const float* b1      = (const float*)d_in[7];
    const float* W2s     = (const float*)d_in[8];
    const float* W2n     = (const float*)d_in[9];
    const float* b2      = (const float*)d_in[10];
    const float* Wfc     = (const float*)d_in[11];
    const float* bfc     = (const float*)d_in[12];
    float* out = (float*)d_out;

    int N = in_sizes[0] / F;
    int E = in_sizes[1];
    int S = in_sizes[3];

    // CSR build (per launch; identical work every call)
    k_zero_deg<<<(N + 255) / 256, 256>>>(N);
    k_count_deg<<<(E + 255) / 256, 256>>>(edst, E);
    k_scan<<<1, 1024>>>(N, E);
    k_fill_adj<<<(E + 255) / 256, 256>>>(esrc, edst, E);

    int gemm_blocks = (N + 127) / 128;
    int agg_blocks = (N + 3) / 4;

    // Layer 1
    k_agg_mean<<<agg_blocks, 128>>>(x, 0, N);
    k_gemm2<<<gemm_blocks, 256>>>(x, W1s, W1n, b1, N, 0);

    // Layer 2
    k_agg_mean<<<agg_blocks, 128>>>(x, 1, N);
    k_gemm2<<<gemm_blocks, 256>>>(x, W2s, W2n, b2, N, 1);

    // Readout
    k_readout<<<1, 128>>>(states, S, actions, Wfc, bfc, out);
}